// round 9
// baseline (speedup 1.0000x reference)
#include <cuda_runtime.h>
#include <cuda_bf16.h>

// Soft local histogram, R=5, bandwidth=0.5.
// Input/output: (4, 8, 3, 256, 256) fp32 -> 96 images of 256x256.
// out[y,x] = sum_{di,dj in [-2,2]} max(0, 1 - 2*|x[y+di,x+dj] - x[y,x]|)
// for y,x in [2, 254); zero on the 2-pixel border.
//
// Tap math (issue floor, 3 FFMA-imm per tap, zero alu ops):
//   d   = fmaf(a, 2.0f, -2c)                    // FFMA-imm (rt=1)
//   w   = __saturatef(fmaf(|d|, -1.0f, 1.0f))   // FFMA.SAT-imm (sat == relu)
//   acc = fmaf(w, 2.0f, acc)                    // FFMA-imm
// PX=4 x-vectorization: 12-float row window -> 3x LDS.128, outputs STG.128.
// This round: 7 CTAs/SM (36-reg cap) — R6/R7/R8 established the occ->issue
// curve; pushing occupancy 65% -> ~75% is the remaining live lever.

#define IMG_H 256
#define IMG_W 256
#define TX 8            // threads in x; each covers PX=4 pixels -> 32 wide
#define TYB 32
#define PX 4
#define PY 2
#define BW 32           // block tile width in pixels
#define BH (TYB * PY)   // 64 output rows per block
#define TILE_H (BH + 4) // 68
#define TILE_W 56       // cols: [0..3] pad, [4..51] loaded, [52..55] pad
#define NF4 12          // float4s loaded per row (48 floats, s in [4,52))
#define NLOAD (TILE_H * NF4)   // 816

__global__ __launch_bounds__(TX * TYB, 7) void soft_hist_kernel(
    const float* __restrict__ in, float* __restrict__ out)
{
    __shared__ float tile[TILE_H][TILE_W];

    const int img = blockIdx.z;
    const float* im = in + (size_t)img * IMG_H * IMG_W;
    float* om = out + (size_t)img * IMG_H * IMG_W;

    const int x0 = blockIdx.x * BW;
    const int y0 = blockIdx.y * BH;
    const int tx = threadIdx.x;
    const int ty = threadIdx.y;
    const int tid = ty * TX + tx;

    // 48-float aligned load window starting at base_x; smem col s = g - base_x + 4.
    // Edge clamps shift the window; pad/garbage cols only ever feed taps whose
    // outputs are in the forced-zero border (verified by index enumeration).
    int base_x = x0 - 8;
    if (base_x < 0) base_x = 0;
    if (base_x > IMG_W - 48) base_x = IMG_W - 48;   // 208

    for (int idx = tid; idx < NLOAD; idx += TX * TYB) {
        int ly = idx / NF4;
        int lf = idx - ly * NF4;
        int gy = min(max(y0 + ly - 2, 0), IMG_H - 1);   // clamped rows feed zeros
        float4 v = *reinterpret_cast<const float4*>(im + gy * IMG_W + base_x + lf * 4);
        *reinterpret_cast<float4*>(&tile[ly][4 + lf * 4]) = v;
    }
    __syncthreads();

    // Thread outputs: cols x0 + 4*tx + p (p=0..3), rows y0 + ty*PY + k (k=0..1).
    // Tap window per row: 12 floats, smem cols [scol0-4, scol0+8), 16B aligned.
    const int scol0 = (x0 + PX * tx) - base_x + 4;   // smem col of output p=0
    const int rbase = ty * PY;
    const float one = 1.0f;

    // Centers: rows rbase+2..rbase+3, cols scol0..scol0+3 -> one LDS.128 each.
    float nc2[PY * PX];
    float acc[PY * PX];
    #pragma unroll
    for (int k = 0; k < PY; k++) {
        float4 c = *reinterpret_cast<const float4*>(&tile[rbase + k + 2][scol0]);
        nc2[k * PX + 0] = -2.0f * c.x;
        nc2[k * PX + 1] = -2.0f * c.y;
        nc2[k * PX + 2] = -2.0f * c.z;
        nc2[k * PX + 3] = -2.0f * c.w;
        acc[k * PX + 0] = 2.0f;   // center tap (w==1) pre-seeded, x2 scale
        acc[k * PX + 1] = 2.0f;
        acc[k * PX + 2] = 2.0f;
        acc[k * PX + 3] = 2.0f;
    }

    // Slide over PY+4 tap rows; 3x LDS.128 per row serve all 4 x-outputs.
    #pragma unroll
    for (int ry = 0; ry < PY + 4; ry++) {
        float a[12];
        #pragma unroll
        for (int q = 0; q < 3; q++) {
            float4 v = *reinterpret_cast<const float4*>(&tile[rbase + ry][scol0 - 4 + q * 4]);
            a[q * 4 + 0] = v.x; a[q * 4 + 1] = v.y;
            a[q * 4 + 2] = v.z; a[q * 4 + 3] = v.w;
        }
        // a[i] holds global col (x0 + 4*tx - 4 + i); tap (p, j) -> a[p + 2 + j].
        #pragma unroll
        for (int k = 0; k < PY; k++) {
            if (ry >= k && ry <= k + 4) {
                #pragma unroll
                for (int p = 0; p < PX; p++) {
                    #pragma unroll
                    for (int j = 0; j < 5; j++) {
                        if (ry == k + 2 && j == 2) continue;   // center: skipped
                        float d = fmaf(a[p + 2 + j], 2.0f, nc2[k * PX + p]);   // FFMA-imm
                        float w = __saturatef(fmaf(fabsf(d), -1.0f, one));     // FFMA.SAT
                        acc[k * PX + p] = fmaf(w, 2.0f, acc[k * PX + p]);      // FFMA-imm
                    }
                }
            }
        }
    }

    // Epilogue: border select + 0.5x scale, one STG.128 per output row.
    const int gxb = x0 + PX * tx;
    #pragma unroll
    for (int k = 0; k < PY; k++) {
        int gy = y0 + rbase + k;
        bool yin = (gy >= 2) && (gy < IMG_H - 2);
        float4 v;
        v.x = (yin && gxb + 0 >= 2 && gxb + 0 < IMG_W - 2) ? 0.5f * acc[k * PX + 0] : 0.0f;
        v.y = (yin && gxb + 1 >= 2 && gxb + 1 < IMG_W - 2) ? 0.5f * acc[k * PX + 1] : 0.0f;
        v.z = (yin && gxb + 2 >= 2 && gxb + 2 < IMG_W - 2) ? 0.5f * acc[k * PX + 2] : 0.0f;
        v.w = (yin && gxb + 3 >= 2 && gxb + 3 < IMG_W - 2) ? 0.5f * acc[k * PX + 3] : 0.0f;
        *reinterpret_cast<float4*>(om + gy * IMG_W + gxb) = v;
    }
}

extern "C" void kernel_launch(void* const* d_in, const int* in_sizes, int n_in,
                              void* d_out, int out_size) {
    const float* in = (const float*)d_in[0];
    float* out = (float*)d_out;
    dim3 block(TX, TYB, 1);
    dim3 grid(IMG_W / BW, IMG_H / BH, 96);   // 8 x 4 x 96 = 3072 blocks
    soft_hist_kernel<<<grid, block>>>(in, out);
}

// round 10
// speedup vs baseline: 1.0771x; 1.0771x over previous
#include <cuda_runtime.h>
#include <cuda_bf16.h>

// Soft local histogram, R=5, bandwidth=0.5.
// Input/output: (4, 8, 3, 256, 256) fp32 -> 96 images of 256x256.
// out[y,x] = sum_{di,dj in [-2,2]} max(0, 1 - 2*|x[y+di,x+dj] - x[y,x]|)
// for y,x in [2, 254); zero on the 2-pixel border.
//
// Tap math (issue floor, 3 FFMA-imm per tap):
//   d   = fmaf(a, 2.0f, -2c); w = __saturatef(fmaf(|d|,-1,1)); acc = fmaf(w,2,acc)
// This round: exact 8-float row window (LDS.64 + LDS.128 + LDS.64) cuts live
// registers so the kernel fits the 32-reg bin WITHOUT spills, enabling
// 7 CTAs/SM = 1792 resident threads -> 2.96 waves (was 3.46, 13.5% tail waste).

#define IMG_H 256
#define IMG_W 256
#define TX 8            // threads in x; each covers PX=4 pixels -> 32 wide
#define TYB 32
#define PX 4
#define PY 2
#define BW 32           // block tile width in pixels
#define BH (TYB * PY)   // 64 output rows per block
#define TILE_H (BH + 4) // 68
#define TILE_W 56       // cols: [0..3] pad, [4..51] loaded, [52..55] pad
#define NF4 12          // float4s loaded per row (48 floats, s in [4,52))
#define NLOAD (TILE_H * NF4)   // 816

__global__ __launch_bounds__(TX * TYB, 7) void soft_hist_kernel(
    const float* __restrict__ in, float* __restrict__ out)
{
    __shared__ float tile[TILE_H][TILE_W];

    const int img = blockIdx.z;
    const float* im = in + (size_t)img * IMG_H * IMG_W;
    float* om = out + (size_t)img * IMG_H * IMG_W;

    const int x0 = blockIdx.x * BW;
    const int y0 = blockIdx.y * BH;
    const int tx = threadIdx.x;
    const int ty = threadIdx.y;
    const int tid = ty * TX + tx;

    // 48-float aligned load window starting at base_x; smem col s = g - base_x + 4.
    // Edge clamps shift the window; pad/garbage cols only ever feed taps whose
    // outputs are in the forced-zero border (verified by index enumeration).
    int base_x = x0 - 8;
    if (base_x < 0) base_x = 0;
    if (base_x > IMG_W - 48) base_x = IMG_W - 48;   // 208

    for (int idx = tid; idx < NLOAD; idx += TX * TYB) {
        int ly = idx / NF4;
        int lf = idx - ly * NF4;
        int gy = min(max(y0 + ly - 2, 0), IMG_H - 1);   // clamped rows feed zeros
        float4 v = *reinterpret_cast<const float4*>(im + gy * IMG_W + base_x + lf * 4);
        *reinterpret_cast<float4*>(&tile[ly][4 + lf * 4]) = v;
    }
    __syncthreads();

    // Thread outputs: cols x0 + 4*tx + p (p=0..3), rows y0 + ty*PY + k (k=0..1).
    // Exact tap window per row: 8 floats, smem cols [scol0-2, scol0+6).
    // scol0 is 4-aligned and scol0-2 is 2-aligned for all blocks (base_x is a
    // multiple of 16 away from x0 in all clamp cases), so LDS.64/128 are legal.
    const int scol0 = (x0 + PX * tx) - base_x + 4;   // smem col of output p=0
    const int rbase = ty * PY;
    const float one = 1.0f;

    // Centers: rows rbase+2..rbase+3, cols scol0..scol0+3 -> one LDS.128 each.
    float nc2[PY * PX];
    float acc[PY * PX];
    #pragma unroll
    for (int k = 0; k < PY; k++) {
        float4 c = *reinterpret_cast<const float4*>(&tile[rbase + k + 2][scol0]);
        nc2[k * PX + 0] = -2.0f * c.x;
        nc2[k * PX + 1] = -2.0f * c.y;
        nc2[k * PX + 2] = -2.0f * c.z;
        nc2[k * PX + 3] = -2.0f * c.w;
        acc[k * PX + 0] = 2.0f;   // center tap (w==1) pre-seeded, x2 scale
        acc[k * PX + 1] = 2.0f;
        acc[k * PX + 2] = 2.0f;
        acc[k * PX + 3] = 2.0f;
    }

    // Slide over PY+4 tap rows; exactly-needed 8 floats per row, 3 LDS issues.
    #pragma unroll
    for (int ry = 0; ry < PY + 4; ry++) {
        float a[8];   // a[i] = value at global col gxb - 2 + i
        {
            const float* row = &tile[rbase + ry][0];
            float2 lo = *reinterpret_cast<const float2*>(row + scol0 - 2);
            float4 md = *reinterpret_cast<const float4*>(row + scol0);
            float2 hi = *reinterpret_cast<const float2*>(row + scol0 + 4);
            a[0] = lo.x; a[1] = lo.y;
            a[2] = md.x; a[3] = md.y; a[4] = md.z; a[5] = md.w;
            a[6] = hi.x; a[7] = hi.y;
        }
        // Tap (p, j) reads global col gxb + p + j - 2 -> a[p + j].
        #pragma unroll
        for (int k = 0; k < PY; k++) {
            if (ry >= k && ry <= k + 4) {
                #pragma unroll
                for (int p = 0; p < PX; p++) {
                    #pragma unroll
                    for (int j = 0; j < 5; j++) {
                        if (ry == k + 2 && j == 2) continue;   // center: skipped
                        float d = fmaf(a[p + j], 2.0f, nc2[k * PX + p]);   // FFMA-imm
                        float w = __saturatef(fmaf(fabsf(d), -1.0f, one)); // FFMA.SAT
                        acc[k * PX + p] = fmaf(w, 2.0f, acc[k * PX + p]);  // FFMA-imm
                    }
                }
            }
        }
    }

    // Epilogue: border select + 0.5x scale, one STG.128 per output row.
    const int gxb = x0 + PX * tx;
    #pragma unroll
    for (int k = 0; k < PY; k++) {
        int gy = y0 + rbase + k;
        bool yin = (gy >= 2) && (gy < IMG_H - 2);
        float4 v;
        v.x = (yin && gxb + 0 >= 2 && gxb + 0 < IMG_W - 2) ? 0.5f * acc[k * PX + 0] : 0.0f;
        v.y = (yin && gxb + 1 >= 2 && gxb + 1 < IMG_W - 2) ? 0.5f * acc[k * PX + 1] : 0.0f;
        v.z = (yin && gxb + 2 >= 2 && gxb + 2 < IMG_W - 2) ? 0.5f * acc[k * PX + 2] : 0.0f;
        v.w = (yin && gxb + 3 >= 2 && gxb + 3 < IMG_W - 2) ? 0.5f * acc[k * PX + 3] : 0.0f;
        *reinterpret_cast<float4*>(om + gy * IMG_W + gxb) = v;
    }
}

extern "C" void kernel_launch(void* const* d_in, const int* in_sizes, int n_in,
                              void* d_out, int out_size) {
    const float* in = (const float*)d_in[0];
    float* out = (float*)d_out;
    dim3 block(TX, TYB, 1);
    dim3 grid(IMG_W / BW, IMG_H / BH, 96);   // 8 x 4 x 96 = 3072 blocks
    soft_hist_kernel<<<grid, block>>>(in, out);
}